// round 1
// baseline (speedup 1.0000x reference)
#include <cuda_runtime.h>
#include <math.h>

// Problem constants
#define N_ATOM 512
#define D_MODEL 512
#define N_HEAD 16
#define K_GAUSS 128
#define M_EDGE 8
#define N_LAYER 4
#define NP1 513           // n + cls
#define HD (N_HEAD * D_MODEL)   // 8192
#define NCELL (N_ATOM * N_ATOM) // 262144

// ---------------- scratch (static device globals; no allocation) -------------
__device__ float g_psi[(size_t)NCELL * K_GAUSS];   // 134 MB
__device__ float g_T[(size_t)NCELL * K_GAUSS];     // 134 MB
__device__ float g_S[N_ATOM * K_GAUSS];
__device__ float g_bias[(size_t)N_HEAD * NCELL];   // 16.8 MB
__device__ int   g_et[NCELL];
__device__ int   g_deg[N_ATOM];
__device__ float g_x[NP1 * D_MODEL];
__device__ float g_q[(size_t)NP1 * HD];
__device__ float g_k[(size_t)NP1 * HD];
__device__ float g_v[(size_t)NP1 * HD];
__device__ float g_o[(size_t)NP1 * HD];
__device__ float g_attn[(size_t)N_HEAD * NP1 * NP1];
__device__ float g_z[NP1 * D_MODEL];
__device__ float g_h1[NP1 * D_MODEL];

// ---------------- small utility kernels --------------------------------------
__global__ void zero_int_kernel(int* p, int n) {
    int i = blockIdx.x * blockDim.x + threadIdx.x;
    if (i < n) p[i] = 0;
}

// Ordered scatter, matching sequential last-write-wins semantics:
// first all (f,t), then all (t,f).
__global__ void scatter_kernel(const int* __restrict__ edge_index,
                               const int* __restrict__ types, int E_) {
    if (blockIdx.x == 0 && threadIdx.x == 0) {
        for (int e = 0; e < E_; e++)
            g_et[edge_index[e] * N_ATOM + edge_index[E_ + e]] = types[e];
        for (int e = 0; e < E_; e++)
            g_et[edge_index[E_ + e] * N_ATOM + edge_index[e]] = types[e];
    }
}

__global__ void degree_kernel() {
    int i = blockIdx.x;
    int c = 0;
    for (int j = threadIdx.x; j < N_ATOM; j += 256)
        c += (g_et[i * N_ATOM + j] != 0);
    __shared__ int sh[256];
    sh[threadIdx.x] = c;
    __syncthreads();
    for (int s = 128; s > 0; s >>= 1) {
        if (threadIdx.x < s) sh[threadIdx.x] += sh[threadIdx.x + s];
        __syncthreads();
    }
    if (threadIdx.x == 0) g_deg[i] = sh[0];
}

// psi_3d[i,j,k] = 1/(sqrt(2pi)*std_k) * exp(-0.5*((gamma*dist+beta-mean_k)/std_k)^2)
__global__ void psi_kernel(const float* __restrict__ pos,
                           const float* __restrict__ gamma_tab,
                           const float* __restrict__ beta_tab,
                           const float* __restrict__ means,
                           const float* __restrict__ stds) {
    long cell = blockIdx.x;
    int k = threadIdx.x;
    int i = (int)(cell >> 9), j = (int)(cell & 511);
    float dx = pos[i * 3 + 0] - pos[j * 3 + 0];
    float dy = pos[i * 3 + 1] - pos[j * 3 + 1];
    float dz = pos[i * 3 + 2] - pos[j * 3 + 2];
    float dist = sqrtf(dx * dx + dy * dy + dz * dz + 1e-12f);
    int t = g_et[cell];
    float xg = gamma_tab[t] * dist + beta_tab[t];
    float sd = fabsf(stds[k]) + 0.01f;
    float u = (xg - means[k]) / sd;
    g_psi[cell * K_GAUSS + k] = (0.3989422804014327f / sd) * expf(-0.5f * u * u);
}

// S[i,k] = sum_j psi[i,j,k]
__global__ void psi_rowsum_kernel() {
    int i = blockIdx.x;
    int k = threadIdx.x; // 128
    float acc = 0.f;
    const float* base = g_psi + (size_t)i * N_ATOM * K_GAUSS + k;
    #pragma unroll 8
    for (int j = 0; j < N_ATOM; j++) acc += base[(size_t)j * K_GAUSS];
    g_S[i * K_GAUSS + k] = acc;
}

// bias[h,i,j] = phi_spd + phi_edge + phi_3d   (phi_3d = gelu(psi@pW1^T) @ pW2^T fused here)
__global__ void bias_kernel(const int* __restrict__ spatial_pos,
                            const int* __restrict__ edge_input,
                            const float* __restrict__ spd_tab,
                            const float* __restrict__ edge_tab,
                            const float* __restrict__ edge_dis,
                            const float* __restrict__ pW2) {
    __shared__ float ew_s[M_EDGE * 256];      // [m][hh][h]
    __shared__ float etab_s[32 * 16];
    __shared__ float pW2_s[16 * 128];
    __shared__ float T_s[16][129];
    int tid = threadIdx.x; // 256
    for (int i = tid; i < M_EDGE * 256; i += 256) ew_s[i] = edge_dis[i];
    for (int i = tid; i < 32 * 16; i += 256) etab_s[i] = edge_tab[i];
    for (int i = tid; i < 16 * 128; i += 256) pW2_s[i] = pW2[i];
    long cell0 = (long)blockIdx.x * 16;
    for (int i = tid; i < 16 * 128; i += 256)
        T_s[i / 128][i % 128] = g_T[cell0 * K_GAUSS + i];
    __syncthreads();
    int cl = tid & 15, h = tid >> 4;
    long cell = cell0 + cl;
    float acc = 0.f;
    #pragma unroll 8
    for (int k = 0; k < 128; k++) acc += T_s[cl][k] * pW2_s[h * 128 + k];
    int sp = spatial_pos[cell];
    acc += spd_tab[sp * 16 + h];
    float esum = 0.f;
    for (int m = 0; m < M_EDGE; m++) {
        int ei = edge_input[cell * M_EDGE + m];
        const float* ewm = &ew_s[m * 256];
        #pragma unroll
        for (int hh = 0; hh < 16; hh++)
            esum += etab_s[ei * 16 + hh] * ewm[hh * 16 + h];
    }
    float spf = (sp == 0) ? 1.f : (float)sp;
    acc += esum / spf;
    g_bias[(size_t)h * NCELL + cell] = acc;
}

// x[0,:] = cls; x[1+i,d] = atoms_x + atom_tab[atoms] + degree_tab[deg] + S@w3d^T
__global__ void xinit_kernel(const float* __restrict__ atoms_x,
                             const int* __restrict__ atoms,
                             const float* __restrict__ atom_tab,
                             const float* __restrict__ degree_tab,
                             const float* __restrict__ w3d,
                             const float* __restrict__ cls) {
    int i = blockIdx.x;
    __shared__ float Ssh[128];
    if (threadIdx.x < 128) Ssh[threadIdx.x] = g_S[i * K_GAUSS + threadIdx.x];
    __syncthreads();
    int a = atoms[i], dgi = g_deg[i];
    for (int d = threadIdx.x; d < D_MODEL; d += blockDim.x) {
        float acc = 0.f;
        const float* wrow = w3d + (size_t)d * K_GAUSS;
        #pragma unroll 8
        for (int k = 0; k < 128; k++) acc += Ssh[k] * wrow[k];
        g_x[(i + 1) * D_MODEL + d] = atoms_x[i * D_MODEL + d]
                                   + atom_tab[a * D_MODEL + d]
                                   + degree_tab[dgi * D_MODEL + d] + acc;
    }
    if (i == 0)
        for (int d = threadIdx.x; d < D_MODEL; d += blockDim.x)
            g_x[d] = cls[d];
}

// ---------------- generic fp32 GEMM -------------------------------------------
// C = alpha * A @ op(B) (+ epilogue). EPI: 0 none, 1 gelu, 2 add attn-bias.
// BT=true: C[m,n] = sum_k A[m,k]*B[n,k];  BT=false: sum_k A[m,k]*B[k,n]
template <int EPI, bool BT>
__global__ void gemm_kernel(const float* __restrict__ Ag, const float* __restrict__ Bg,
                            float* __restrict__ Cg, const float* __restrict__ biasg,
                            int M, int N, int K, int lda, int ldb, int ldc,
                            long sA, long sB, long sC, long sBias, float alpha) {
    int bz = blockIdx.z;
    const float* A = Ag + (long)bz * sA;
    const float* B = Bg + (long)bz * sB;
    float* C = Cg + (long)bz * sC;
    const float* bias = (EPI == 2) ? (biasg + (long)bz * sBias) : nullptr;

    __shared__ float As[16][68];
    __shared__ float Bs[16][68];

    int bm = blockIdx.y * 64;
    int bn = blockIdx.x * 64;
    int tid = threadIdx.x;
    int tx = tid & 15, ty = tid >> 4;

    float acc[4][4] = {};
    for (int k0 = 0; k0 < K; k0 += 16) {
        #pragma unroll
        for (int it = 0; it < 4; it++) {
            int lm = (tid >> 4) + it * 16;
            int lk = tid & 15;
            int gm = bm + lm, gk = k0 + lk;
            As[lk][lm] = (gm < M && gk < K) ? A[(long)gm * lda + gk] : 0.f;
        }
        if (BT) {
            #pragma unroll
            for (int it = 0; it < 4; it++) {
                int ln = (tid >> 4) + it * 16;
                int lk = tid & 15;
                int gn = bn + ln, gk = k0 + lk;
                Bs[lk][ln] = (gn < N && gk < K) ? B[(long)gn * ldb + gk] : 0.f;
            }
        } else {
            #pragma unroll
            for (int it = 0; it < 4; it++) {
                int ln = tid & 63;
                int lk = (tid >> 6) + it * 4;
                int gn = bn + ln, gk = k0 + lk;
                Bs[lk][ln] = (gn < N && gk < K) ? B[(long)gk * ldb + gn] : 0.f;
            }
        }
        __syncthreads();
        #pragma unroll
        for (int kk = 0; kk < 16; kk++) {
            float a[4], b[4];
            #pragma unroll
            for (int i = 0; i < 4; i++) a[i] = As[kk][ty * 4 + i];
            #pragma unroll
            for (int j = 0; j < 4; j++) b[j] = Bs[kk][tx * 4 + j];
            #pragma unroll
            for (int i = 0; i < 4; i++)
                #pragma unroll
                for (int j = 0; j < 4; j++) acc[i][j] = fmaf(a[i], b[j], acc[i][j]);
        }
        __syncthreads();
    }
    #pragma unroll
    for (int i = 0; i < 4; i++) {
        int gm = bm + ty * 4 + i;
        if (gm >= M) continue;
        #pragma unroll
        for (int j = 0; j < 4; j++) {
            int gn = bn + tx * 4 + j;
            if (gn >= N) continue;
            float vv = acc[i][j] * alpha;
            if (EPI == 1) {
                vv = 0.5f * vv * (1.f + erff(vv * 0.7071067811865476f));
            } else if (EPI == 2) {
                if (gm >= 1 && gn >= 1)
                    vv += bias[(long)(gm - 1) * N_ATOM + (gn - 1)];
            }
            C[(long)gm * ldc + gn] = vv;
        }
    }
}

// ---------------- softmax over rows of length 513 ------------------------------
__global__ void softmax_kernel() {
    long row = blockIdx.x;
    float* p = g_attn + row * NP1;
    int tid = threadIdx.x; // 256
    __shared__ float sh[256];
    float mx = -1e30f;
    for (int m = tid; m < NP1; m += 256) mx = fmaxf(mx, p[m]);
    sh[tid] = mx; __syncthreads();
    for (int s = 128; s > 0; s >>= 1) {
        if (tid < s) sh[tid] = fmaxf(sh[tid], sh[tid + s]);
        __syncthreads();
    }
    mx = sh[0]; __syncthreads();
    float sum = 0.f;
    for (int m = tid; m < NP1; m += 256) {
        float e = expf(p[m] - mx);
        p[m] = e;
        sum += e;
    }
    sh[tid] = sum; __syncthreads();
    for (int s = 128; s > 0; s >>= 1) {
        if (tid < s) sh[tid] += sh[tid + s];
        __syncthreads();
    }
    float inv = 1.f / sh[0];
    __syncthreads();
    for (int m = tid; m < NP1; m += 256) p[m] *= inv;
}

// ---------------- residual add + layernorm ------------------------------------
__global__ void add_ln_kernel(const float* __restrict__ xin, const float* __restrict__ z,
                              const float* __restrict__ s, const float* __restrict__ b,
                              float* __restrict__ xout) {
    int row = blockIdx.x, tid = threadIdx.x; // 256 threads, 512 cols
    float v0 = xin[row * D_MODEL + tid] + z[row * D_MODEL + tid];
    float v1 = xin[row * D_MODEL + tid + 256] + z[row * D_MODEL + tid + 256];
    __shared__ float sh[256];
    sh[tid] = v0 + v1; __syncthreads();
    for (int st = 128; st > 0; st >>= 1) {
        if (tid < st) sh[tid] += sh[tid + st];
        __syncthreads();
    }
    float mu = sh[0] * (1.f / D_MODEL);
    __syncthreads();
    float d0 = v0 - mu, d1 = v1 - mu;
    sh[tid] = d0 * d0 + d1 * d1; __syncthreads();
    for (int st = 128; st > 0; st >>= 1) {
        if (tid < st) sh[tid] += sh[tid + st];
        __syncthreads();
    }
    float rstd = rsqrtf(sh[0] * (1.f / D_MODEL) + 1e-5f);
    xout[row * D_MODEL + tid]       = d0 * rstd * s[tid]       + b[tid];
    xout[row * D_MODEL + tid + 256] = d1 * rstd * s[tid + 256] + b[tid + 256];
}

// ---------------- host launch ---------------------------------------------------
static inline dim3 gemm_grid(int M, int N, int batch) {
    return dim3((N + 63) / 64, (M + 63) / 64, batch);
}

extern "C" void kernel_launch(void* const* d_in, const int* in_sizes, int n_in,
                              void* d_out, int out_size) {
    const float* atoms_x  = (const float*)d_in[0];
    const float* pos      = (const float*)d_in[1];
    const int*   atoms    = (const int*)d_in[2];
    const int*   edge_index = (const int*)d_in[3];
    const int*   edge_attr_types = (const int*)d_in[4];
    const int*   spatial_pos = (const int*)d_in[5];
    const int*   edge_input  = (const int*)d_in[6];
    const float* atom_tab   = (const float*)d_in[7];
    const float* degree_tab = (const float*)d_in[8];
    const float* w3d        = (const float*)d_in[9];
    const float* spd_tab    = (const float*)d_in[10];
    const float* edge_tab   = (const float*)d_in[11];
    const float* edge_dis   = (const float*)d_in[12];
    const float* means      = (const float*)d_in[13];
    const float* stds       = (const float*)d_in[14];
    const float* gamma_tab  = (const float*)d_in[15];
    const float* beta_tab   = (const float*)d_in[16];
    const float* pW1        = (const float*)d_in[17];
    const float* pW2        = (const float*)d_in[18];
    const float* cls        = (const float*)d_in[19];
    const float* Qw         = (const float*)d_in[20];
    const float* Kw         = (const float*)d_in[21];
    const float* Vw         = (const float*)d_in[22];
    const float* Wout       = (const float*)d_in[23];
    const float* F1         = (const float*)d_in[24];
    const float* F2         = (const float*)d_in[25];
    const float* ln1_s      = (const float*)d_in[26];
    const float* ln1_b      = (const float*)d_in[27];
    const float* ln2_s      = (const float*)d_in[28];
    const float* ln2_b      = (const float*)d_in[29];
    float* out = (float*)d_out;

    float *psi, *T, *bias, *x, *q, *k, *v, *o, *attn, *z, *h1;
    int *et;
    cudaGetSymbolAddress((void**)&psi,  g_psi);
    cudaGetSymbolAddress((void**)&T,    g_T);
    cudaGetSymbolAddress((void**)&bias, g_bias);
    cudaGetSymbolAddress((void**)&x,    g_x);
    cudaGetSymbolAddress((void**)&q,    g_q);
    cudaGetSymbolAddress((void**)&k,    g_k);
    cudaGetSymbolAddress((void**)&v,    g_v);
    cudaGetSymbolAddress((void**)&o,    g_o);
    cudaGetSymbolAddress((void**)&attn, g_attn);
    cudaGetSymbolAddress((void**)&z,    g_z);
    cudaGetSymbolAddress((void**)&h1,   g_h1);
    cudaGetSymbolAddress((void**)&et,   g_et);

    const float scaling = 0.17677669529663687f; // (512/16)^-0.5

    // ---- graph preprocessing ----
    zero_int_kernel<<<(NCELL + 255) / 256, 256>>>(et, NCELL);
    scatter_kernel<<<1, 1>>>(edge_index, edge_attr_types, 2048);
    degree_kernel<<<N_ATOM, 256>>>();
    psi_kernel<<<NCELL, K_GAUSS>>>(pos, gamma_tab, beta_tab, means, stds);
    psi_rowsum_kernel<<<N_ATOM, K_GAUSS>>>();
    // T = gelu(psi @ pW1^T)   [262144,128] x [128,128]
    gemm_kernel<1, true><<<gemm_grid(NCELL, K_GAUSS, 1), 256>>>(
        psi, pW1, T, nullptr, NCELL, K_GAUSS, K_GAUSS, K_GAUSS, K_GAUSS, K_GAUSS,
        0, 0, 0, 0, 1.f);
    bias_kernel<<<NCELL / 16, 256>>>(spatial_pos, edge_input, spd_tab, edge_tab,
                                     edge_dis, pW2);
    xinit_kernel<<<N_ATOM, 256>>>(atoms_x, atoms, atom_tab, degree_tab, w3d, cls);

    // ---- transformer layers ----
    for (int l = 0; l < N_LAYER; l++) {
        const float* Qwl = Qw + (size_t)l * HD * D_MODEL;
        const float* Kwl = Kw + (size_t)l * HD * D_MODEL;
        const float* Vwl = Vw + (size_t)l * HD * D_MODEL;
        const float* Woutl = Wout + (size_t)l * D_MODEL * HD;
        const float* F1l = F1 + (size_t)l * D_MODEL * D_MODEL;
        const float* F2l = F2 + (size_t)l * D_MODEL * D_MODEL;

        // Q/K/V: [513,512] @ [8192,512]^T -> [513,8192]
        gemm_kernel<0, true><<<gemm_grid(NP1, HD, 1), 256>>>(
            x, Qwl, q, nullptr, NP1, HD, D_MODEL, D_MODEL, D_MODEL, HD, 0, 0, 0, 0, 1.f);
        gemm_kernel<0, true><<<gemm_grid(NP1, HD, 1), 256>>>(
            x, Kwl, k, nullptr, NP1, HD, D_MODEL, D_MODEL, D_MODEL, HD, 0, 0, 0, 0, 1.f);
        gemm_kernel<0, true><<<gemm_grid(NP1, HD, 1), 256>>>(
            x, Vwl, v, nullptr, NP1, HD, D_MODEL, D_MODEL, D_MODEL, HD, 0, 0, 0, 0, 1.f);

        // scores: per-head Q_h @ K_h^T * scale + bias  -> attn [16,513,513]
        gemm_kernel<2, true><<<gemm_grid(NP1, NP1, N_HEAD), 256>>>(
            q, k, attn, bias, NP1, NP1, D_MODEL, HD, HD, NP1,
            D_MODEL, D_MODEL, (long)NP1 * NP1, (long)NCELL, scaling);

        softmax_kernel<<<N_HEAD * NP1, 256>>>();

        // O_h = attn_h @ V_h   (NN) -> o [513, 8192]
        gemm_kernel<0, false><<<gemm_grid(NP1, D_MODEL, N_HEAD), 256>>>(
            attn, v, o, nullptr, NP1, D_MODEL, NP1, NP1, HD, HD,
            (long)NP1 * NP1, D_MODEL, D_MODEL, 0, 1.f);

        // z = o @ Wout^T : [513,8192] @ [512,8192]^T
        gemm_kernel<0, true><<<gemm_grid(NP1, D_MODEL, 1), 256>>>(
            o, Woutl, z, nullptr, NP1, D_MODEL, HD, HD, HD, D_MODEL, 0, 0, 0, 0, 1.f);

        add_ln_kernel<<<NP1, 256>>>(x, z, ln1_s + l * D_MODEL, ln1_b + l * D_MODEL, x);

        // FF
        gemm_kernel<1, true><<<gemm_grid(NP1, D_MODEL, 1), 256>>>(
            x, F1l, h1, nullptr, NP1, D_MODEL, D_MODEL, D_MODEL, D_MODEL, D_MODEL,
            0, 0, 0, 0, 1.f);
        gemm_kernel<0, true><<<gemm_grid(NP1, D_MODEL, 1), 256>>>(
            h1, F2l, z, nullptr, NP1, D_MODEL, D_MODEL, D_MODEL, D_MODEL, D_MODEL,
            0, 0, 0, 0, 1.f);

        float* lnout = (l == N_LAYER - 1) ? out : x;
        add_ln_kernel<<<NP1, 256>>>(x, z, ln2_s + l * D_MODEL, ln2_b + l * D_MODEL, lnout);
    }
}

// round 3
// speedup vs baseline: 1.3341x; 1.3341x over previous
#include <cuda_runtime.h>
#include <cuda_bf16.h>
#include <math.h>
#include <stdint.h>

// Problem constants
#define N_ATOM 512
#define D_MODEL 512
#define N_HEAD 16
#define K_GAUSS 128
#define M_EDGE 8
#define N_LAYER 4
#define NP1 513           // n + cls
#define HD (N_HEAD * D_MODEL)   // 8192
#define NCELL (N_ATOM * N_ATOM) // 262144

// ---------------- scratch (static device globals; no allocation) -------------
__device__ float g_psi[(size_t)NCELL * K_GAUSS];   // 134 MB
__device__ float g_T[(size_t)NCELL * K_GAUSS];     // 134 MB
__device__ float g_S[N_ATOM * K_GAUSS];
__device__ float g_bias[(size_t)N_HEAD * NCELL];   // 16.8 MB
__device__ int   g_et[NCELL];
__device__ int   g_deg[N_ATOM];
__device__ float g_x[NP1 * D_MODEL];
__device__ float g_q[(size_t)NP1 * HD];
__device__ float g_k[(size_t)NP1 * HD];
__device__ float g_v[(size_t)NP1 * HD];
__device__ float g_o[(size_t)NP1 * HD];
__device__ float g_attn[(size_t)N_HEAD * NP1 * NP1];
__device__ float g_z[NP1 * D_MODEL];
__device__ float g_h1[NP1 * D_MODEL];

// ---------------- small utility kernels --------------------------------------
__global__ void zero_int_kernel(int* p, int n) {
    int i = blockIdx.x * blockDim.x + threadIdx.x;
    if (i < n) p[i] = 0;
}
__global__ void zero_float_kernel(float* p, int n) {
    int i = blockIdx.x * blockDim.x + threadIdx.x;
    if (i < n) p[i] = 0.f;
}

// Ordered scatter, matching sequential last-write-wins semantics
__global__ void scatter_kernel(const int* __restrict__ edge_index,
                               const int* __restrict__ types, int E_) {
    if (blockIdx.x == 0 && threadIdx.x == 0) {
        for (int e = 0; e < E_; e++)
            g_et[edge_index[e] * N_ATOM + edge_index[E_ + e]] = types[e];
        for (int e = 0; e < E_; e++)
            g_et[edge_index[E_ + e] * N_ATOM + edge_index[e]] = types[e];
    }
}

__global__ void degree_kernel() {
    int i = blockIdx.x;
    int c = 0;
    for (int j = threadIdx.x; j < N_ATOM; j += 256)
        c += (g_et[i * N_ATOM + j] != 0);
    __shared__ int sh[256];
    sh[threadIdx.x] = c;
    __syncthreads();
    for (int s = 128; s > 0; s >>= 1) {
        if (threadIdx.x < s) sh[threadIdx.x] += sh[threadIdx.x + s];
        __syncthreads();
    }
    if (threadIdx.x == 0) g_deg[i] = sh[0];
}

__global__ void psi_kernel(const float* __restrict__ pos,
                           const float* __restrict__ gamma_tab,
                           const float* __restrict__ beta_tab,
                           const float* __restrict__ means,
                           const float* __restrict__ stds) {
    long cell = blockIdx.x;
    int k = threadIdx.x;
    int i = (int)(cell >> 9), j = (int)(cell & 511);
    float dx = pos[i * 3 + 0] - pos[j * 3 + 0];
    float dy = pos[i * 3 + 1] - pos[j * 3 + 1];
    float dz = pos[i * 3 + 2] - pos[j * 3 + 2];
    float dist = sqrtf(dx * dx + dy * dy + dz * dz + 1e-12f);
    int t = g_et[cell];
    float xg = gamma_tab[t] * dist + beta_tab[t];
    float sd = fabsf(stds[k]) + 0.01f;
    float u = (xg - means[k]) / sd;
    g_psi[cell * K_GAUSS + k] = (0.3989422804014327f / sd) * expf(-0.5f * u * u);
}

__global__ void psi_rowsum_kernel() {
    int i = blockIdx.x;
    int k = threadIdx.x; // 128
    float acc = 0.f;
    const float* base = g_psi + (size_t)i * N_ATOM * K_GAUSS + k;
    #pragma unroll 8
    for (int j = 0; j < N_ATOM; j++) acc += base[(size_t)j * K_GAUSS];
    g_S[i * K_GAUSS + k] = acc;
}

__global__ void bias_kernel(const int* __restrict__ spatial_pos,
                            const int* __restrict__ edge_input,
                            const float* __restrict__ spd_tab,
                            const float* __restrict__ edge_tab,
                            const float* __restrict__ edge_dis,
                            const float* __restrict__ pW2) {
    __shared__ float ew_s[M_EDGE * 256];
    __shared__ float etab_s[32 * 16];
    __shared__ float pW2_s[16 * 128];
    __shared__ float T_s[16][129];
    int tid = threadIdx.x; // 256
    for (int i = tid; i < M_EDGE * 256; i += 256) ew_s[i] = edge_dis[i];
    for (int i = tid; i < 32 * 16; i += 256) etab_s[i] = edge_tab[i];
    for (int i = tid; i < 16 * 128; i += 256) pW2_s[i] = pW2[i];
    long cell0 = (long)blockIdx.x * 16;
    for (int i = tid; i < 16 * 128; i += 256)
        T_s[i / 128][i % 128] = g_T[cell0 * K_GAUSS + i];
    __syncthreads();
    int cl = tid & 15, h = tid >> 4;
    long cell = cell0 + cl;
    float acc = 0.f;
    #pragma unroll 8
    for (int k = 0; k < 128; k++) acc += T_s[cl][k] * pW2_s[h * 128 + k];
    int sp = spatial_pos[cell];
    acc += spd_tab[sp * 16 + h];
    float esum = 0.f;
    for (int m = 0; m < M_EDGE; m++) {
        int ei = edge_input[cell * M_EDGE + m];
        const float* ewm = &ew_s[m * 256];
        #pragma unroll
        for (int hh = 0; hh < 16; hh++)
            esum += etab_s[ei * 16 + hh] * ewm[hh * 16 + h];
    }
    float spf = (sp == 0) ? 1.f : (float)sp;
    acc += esum / spf;
    g_bias[(size_t)h * NCELL + cell] = acc;
}

__global__ void xinit_kernel(const float* __restrict__ atoms_x,
                             const int* __restrict__ atoms,
                             const float* __restrict__ atom_tab,
                             const float* __restrict__ degree_tab,
                             const float* __restrict__ w3d,
                             const float* __restrict__ cls) {
    int i = blockIdx.x;
    __shared__ float Ssh[128];
    if (threadIdx.x < 128) Ssh[threadIdx.x] = g_S[i * K_GAUSS + threadIdx.x];
    __syncthreads();
    int a = atoms[i], dgi = g_deg[i];
    for (int d = threadIdx.x; d < D_MODEL; d += blockDim.x) {
        float acc = 0.f;
        const float* wrow = w3d + (size_t)d * K_GAUSS;
        #pragma unroll 8
        for (int k = 0; k < 128; k++) acc += Ssh[k] * wrow[k];
        g_x[(i + 1) * D_MODEL + d] = atoms_x[i * D_MODEL + d]
                                   + atom_tab[a * D_MODEL + d]
                                   + degree_tab[dgi * D_MODEL + d] + acc;
    }
    if (i == 0)
        for (int d = threadIdx.x; d < D_MODEL; d += blockDim.x)
            g_x[d] = cls[d];
}

// ---------------- tensor-core GEMM (bf16x3 split for ~fp32 precision) ----------
// C = alpha * A @ op(B) (+ epilogue). EPI: 0 none, 1 gelu, 2 attn-bias add.
// BLOAD: 0 -> B is [N][ldb] (BT), 1 -> B is [K][ldb] (NN).
// ATOMIC: atomicAdd into C (for split-K), else plain store.
// Block tile BM x BN (128x128 or 64x64), 8 warps in 2x4 layout, K-chunk = 32.

#define MMA16816(d, a, b) asm volatile( \
    "mma.sync.aligned.m16n8k16.row.col.f32.bf16.bf16.f32 " \
    "{%0,%1,%2,%3},{%4,%5,%6,%7},{%8,%9},{%0,%1,%2,%3};\n" \
    : "+f"(d[0]), "+f"(d[1]), "+f"(d[2]), "+f"(d[3]) \
    : "r"(a[0]), "r"(a[1]), "r"(a[2]), "r"(a[3]), "r"(b[0]), "r"(b[1]))

__device__ __forceinline__ void cvt_split2(__nv_bfloat16* hi, __nv_bfloat16* lo,
                                           float x0, float x1) {
    __nv_bfloat16 h0 = __float2bfloat16(x0);
    __nv_bfloat16 h1 = __float2bfloat16(x1);
    __nv_bfloat16 l0 = __float2bfloat16(x0 - __bfloat162float(h0));
    __nv_bfloat16 l1 = __float2bfloat16(x1 - __bfloat162float(h1));
    *(__nv_bfloat162*)hi = __halves2bfloat162(h0, h1);
    *(__nv_bfloat162*)lo = __halves2bfloat162(l0, l1);
}

template <int BM, int BN, int EPI, int BLOAD, bool ATOMIC>
__global__ __launch_bounds__(256) void mma_gemm(
    const float* __restrict__ Ag, const float* __restrict__ Bg,
    float* __restrict__ Cg, const float* __restrict__ biasg,
    int M, int N, int K, int lda, int ldb, int ldc,
    long sA, long sB, long sC, long sBias, float alpha) {

    constexpr int WM = BM / 2;   // warp tile M
    constexpr int WN = BN / 4;   // warp tile N
    constexpr int MT = WM / 16;  // m16 tiles per warp
    constexpr int NT = WN / 8;   // n8 tiles per warp
    constexpr int KS = 40;       // smem row stride in elems (80B, conflict-free)

    __shared__ __nv_bfloat16 sAhi[BM][KS], sAlo[BM][KS];
    __shared__ __nv_bfloat16 sBhi[BN][KS], sBlo[BN][KS];

    int bz = blockIdx.z;
    const float* A = Ag + (long)bz * sA;
    const float* B = Bg + (long)bz * sB;
    float* C = Cg + (long)bz * sC;
    const float* bias = (EPI == 2) ? (biasg + (long)bz * sBias) : nullptr;

    int bm = blockIdx.y * BM;
    int bn = blockIdx.x * BN;
    int tid = threadIdx.x;
    int wid = tid >> 5, lane = tid & 31;
    int wm = wid >> 2, wn = wid & 3;
    int g = lane >> 2, tg = lane & 3;

    float acc[MT][NT][4];
    #pragma unroll
    for (int i = 0; i < MT; i++)
        #pragma unroll
        for (int j = 0; j < NT; j++)
            #pragma unroll
            for (int t = 0; t < 4; t++) acc[i][j][t] = 0.f;

    for (int k0 = 0; k0 < K; k0 += 32) {
        // ---- stage A: [BM][32] fp32 -> hi/lo bf16
        #pragma unroll 2
        for (int p = tid; p < BM * 16; p += 256) {
            int r = p >> 4, c = (p & 15) * 2;
            int gm = bm + r, gk = k0 + c;
            float x0 = 0.f, x1 = 0.f;
            if (gm < M) {
                const float* ap = A + (long)gm * lda + gk;
                if (gk < K) x0 = ap[0];
                if (gk + 1 < K) x1 = ap[1];
            }
            cvt_split2(&sAhi[r][c], &sAlo[r][c], x0, x1);
        }
        // ---- stage B
        if (BLOAD == 0) {
            #pragma unroll 2
            for (int p = tid; p < BN * 16; p += 256) {
                int r = p >> 4, c = (p & 15) * 2;
                int gn = bn + r, gk = k0 + c;
                float x0 = 0.f, x1 = 0.f;
                if (gn < N) {
                    const float* bp = B + (long)gn * ldb + gk;
                    if (gk < K) x0 = bp[0];
                    if (gk + 1 < K) x1 = bp[1];
                }
                cvt_split2(&sBhi[r][c], &sBlo[r][c], x0, x1);
            }
        } else {
            #pragma unroll 2
            for (int p = tid; p < BN * 32; p += 256) {
                int kk = p / BN, n = p % BN;
                int gn = bn + n, gk = k0 + kk;
                float x = 0.f;
                if (gn < N && gk < K) x = B[(long)gk * ldb + gn];
                __nv_bfloat16 h = __float2bfloat16(x);
                sBhi[n][kk] = h;
                sBlo[n][kk] = __float2bfloat16(x - __bfloat162float(h));
            }
        }
        __syncthreads();

        #pragma unroll
        for (int ks = 0; ks < 2; ks++) {
            int ko = ks * 16;
            uint32_t ah[MT][4], al[MT][4], bh[NT][2], bl[NT][2];
            #pragma unroll
            for (int mt = 0; mt < MT; mt++) {
                int row = wm * WM + mt * 16 + g;
                int cc = ko + tg * 2;
                ah[mt][0] = *(const uint32_t*)&sAhi[row][cc];
                ah[mt][1] = *(const uint32_t*)&sAhi[row + 8][cc];
                ah[mt][2] = *(const uint32_t*)&sAhi[row][cc + 8];
                ah[mt][3] = *(const uint32_t*)&sAhi[row + 8][cc + 8];
                al[mt][0] = *(const uint32_t*)&sAlo[row][cc];
                al[mt][1] = *(const uint32_t*)&sAlo[row + 8][cc];
                al[mt][2] = *(const uint32_t*)&sAlo[row][cc + 8];
                al[mt][3] = *(const uint32_t*)&sAlo[row + 8][cc + 8];
            }
            #pragma unroll
            for (int nt = 0; nt < NT; nt++) {
                int col = wn * WN + nt * 8 + g;
                int cc = ko + tg * 2;
                bh[nt][0] = *(const uint32_t*)&sBhi[col][cc];
                bh[nt][1] = *(const uint32_t*)&sBhi[col][cc + 8];
                bl[nt][0] = *(const uint32_t*)&sBlo[col][cc];
                bl[nt][1] = *(const uint32_t*)&sBlo[col][cc + 8];
            }
            #pragma unroll
            for (int mt = 0; mt < MT; mt++)
                #pragma unroll
                for (int nt = 0; nt < NT; nt++) {
                    MMA16816(acc[mt][nt], ah[mt], bh[nt]);
                    MMA16816(acc[mt][nt], ah[mt], bl[nt]);
                    MMA16816(acc[mt][nt], al[mt], bh[nt]);
                }
        }
        __syncthreads();
    }

    // ---- epilogue
    #pragma unroll
    for (int mt = 0; mt < MT; mt++) {
        #pragma unroll
        for (int nt = 0; nt < NT; nt++) {
            int r0 = bm + wm * WM + mt * 16 + g;
            int c0 = bn + wn * WN + nt * 8 + tg * 2;
            #pragma unroll
            for (int t = 0; t < 4; t++) {
                int gm = r0 + (t >= 2 ? 8 : 0);
                int gn = c0 + (t & 1);
                if (gm >= M || gn >= N) continue;
                float vv = acc[mt][nt][t] * alpha;
                if (EPI == 1) {
                    vv = 0.5f * vv * (1.f + erff(vv * 0.7071067811865476f));
                } else if (EPI == 2) {
                    if (gm >= 1 && gn >= 1)
                        vv += bias[(long)(gm - 1) * N_ATOM + (gn - 1)];
                }
                if (ATOMIC) atomicAdd(&C[(long)gm * ldc + gn], vv);
                else C[(long)gm * ldc + gn] = vv;
            }
        }
    }
}

// ---------------- softmax over rows of length 513 ------------------------------
__global__ void softmax_kernel() {
    long row = blockIdx.x;
    float* p = g_attn + row * NP1;
    int tid = threadIdx.x; // 256
    __shared__ float sh[256];
    float mx = -1e30f;
    for (int m = tid; m < NP1; m += 256) mx = fmaxf(mx, p[m]);
    sh[tid] = mx; __syncthreads();
    for (int s = 128; s > 0; s >>= 1) {
        if (tid < s) sh[tid] = fmaxf(sh[tid], sh[tid + s]);
        __syncthreads();
    }
    mx = sh[0]; __syncthreads();
    float sum = 0.f;
    for (int m = tid; m < NP1; m += 256) {
        float e = expf(p[m] - mx);
        p[m] = e;
        sum += e;
    }
    sh[tid] = sum; __syncthreads();
    for (int s = 128; s > 0; s >>= 1) {
        if (tid < s) sh[tid] += sh[tid + s];
        __syncthreads();
    }
    float inv = 1.f / sh[0];
    __syncthreads();
    for (int m = tid; m < NP1; m += 256) p[m] *= inv;
}

// ---------------- residual add + layernorm ------------------------------------
__global__ void add_ln_kernel(const float* __restrict__ xin, const float* __restrict__ z,
                              const float* __restrict__ s, const float* __restrict__ b,
                              float* __restrict__ xout) {
    int row = blockIdx.x, tid = threadIdx.x; // 256 threads, 512 cols
    float v0 = xin[row * D_MODEL + tid] + z[row * D_MODEL + tid];
    float v1 = xin[row * D_MODEL + tid + 256] + z[row * D_MODEL + tid + 256];
    __shared__ float sh[256];
    sh[tid] = v0 + v1; __syncthreads();
    for (int st = 128; st > 0; st >>= 1) {
        if (tid < st) sh[tid] += sh[tid + st];
        __syncthreads();
    }
    float mu = sh[0] * (1.f / D_MODEL);
    __syncthreads();
    float d0 = v0 - mu, d1 = v1 - mu;
    sh[tid] = d0 * d0 + d1 * d1; __syncthreads();
    for (int st = 128; st > 0; st >>= 1) {
        if (tid < st) sh[tid] += sh[tid + st];
        __syncthreads();
    }
    float rstd = rsqrtf(sh[0] * (1.f / D_MODEL) + 1e-5f);
    xout[row * D_MODEL + tid]       = d0 * rstd * s[tid]       + b[tid];
    xout[row * D_MODEL + tid + 256] = d1 * rstd * s[tid + 256] + b[tid + 256];
}

// ---------------- host launch ---------------------------------------------------
extern "C" void kernel_launch(void* const* d_in, const int* in_sizes, int n_in,
                              void* d_out, int out_size) {
    const float* atoms_x  = (const float*)d_in[0];
    const float* pos      = (const float*)d_in[1];
    const int*   atoms    = (const int*)d_in[2];
    const int*   edge_index = (const int*)d_in[3];
    const int*   edge_attr_types = (const int*)d_in[4];
    const int*   spatial_pos = (const int*)d_in[5];
    const int*   edge_input  = (const int*)d_in[6];
    const float* atom_tab   = (const float*)d_in[7];
    const float* degree_tab = (const float*)d_in[8];
    const float* w3d        = (const float*)d_in[9];
    const float* spd_tab    = (const float*)d_in[10];
    const float* edge_tab   = (const float*)d_in[11];
    const float* edge_dis   = (const float*)d_in[12];
    const float* means      = (const float*)d_in[13];
    const float* stds       = (const float*)d_in[14];
    const float* gamma_tab  = (const float*)d_in[15];
    const float* beta_tab   = (const float*)d_in[16];
    const float* pW1        = (const float*)d_in[17];
    const float* pW2        = (const float*)d_in[18];
    const float* cls        = (const float*)d_in[19];
    const float* Qw         = (const float*)d_in[20];
    const float* Kw         = (const float*)d_in[21];
    const float* Vw         = (const float*)d_in[22];
    const float* Wout       = (const float*)d_in[23];
    const float* F1         = (const float*)d_in[24];
    const float* F2         = (const float*)d_in[25];
    const float* ln1_s      = (const float*)d_in[26];
    const float* ln1_b      = (const float*)d_in[27];
    const float* ln2_s      = (const float*)d_in[28];
    const float* ln2_b      = (const float*)d_in[29];
    float* out = (float*)d_out;

    float *psi, *T, *bias, *x, *q, *k, *v, *o, *attn, *z, *h1;
    int *et;
    cudaGetSymbolAddress((void**)&psi,  g_psi);
    cudaGetSymbolAddress((void**)&T,    g_T);
    cudaGetSymbolAddress((void**)&bias, g_bias);
    cudaGetSymbolAddress((void**)&x,    g_x);
    cudaGetSymbolAddress((void**)&q,    g_q);
    cudaGetSymbolAddress((void**)&k,    g_k);
    cudaGetSymbolAddress((void**)&v,    g_v);
    cudaGetSymbolAddress((void**)&o,    g_o);
    cudaGetSymbolAddress((void**)&attn, g_attn);
    cudaGetSymbolAddress((void**)&z,    g_z);
    cudaGetSymbolAddress((void**)&h1,   g_h1);
    cudaGetSymbolAddress((void**)&et,   g_et);

    const float scaling = 0.17677669529663687f; // (512/16)^-0.5

    // ---- graph preprocessing ----
    zero_int_kernel<<<(NCELL + 255) / 256, 256>>>(et, NCELL);
    scatter_kernel<<<1, 1>>>(edge_index, edge_attr_types, 2048);
    degree_kernel<<<N_ATOM, 256>>>();
    psi_kernel<<<NCELL, K_GAUSS>>>(pos, gamma_tab, beta_tab, means, stds);
    psi_rowsum_kernel<<<N_ATOM, K_GAUSS>>>();
    // T = gelu(psi @ pW1^T)   [262144,128] x [128,128]^T
    mma_gemm<128, 128, 1, 0, false><<<dim3(1, NCELL / 128, 1), 256>>>(
        psi, pW1, T, nullptr, NCELL, K_GAUSS, K_GAUSS, K_GAUSS, K_GAUSS, K_GAUSS,
        0, 0, 0, 0, 1.f);
    bias_kernel<<<NCELL / 16, 256>>>(spatial_pos, edge_input, spd_tab, edge_tab,
                                     edge_dis, pW2);
    xinit_kernel<<<N_ATOM, 256>>>(atoms_x, atoms, atom_tab, degree_tab, w3d, cls);

    // ---- transformer layers ----
    for (int l = 0; l < N_LAYER; l++) {
        const float* Qwl = Qw + (size_t)l * HD * D_MODEL;
        const float* Kwl = Kw + (size_t)l * HD * D_MODEL;
        const float* Vwl = Vw + (size_t)l * HD * D_MODEL;
        const float* Woutl = Wout + (size_t)l * D_MODEL * HD;
        const float* F1l = F1 + (size_t)l * D_MODEL * D_MODEL;
        const float* F2l = F2 + (size_t)l * D_MODEL * D_MODEL;

        // Q/K/V: [513,512] @ [8192,512]^T -> [513,8192]
        mma_gemm<128, 128, 0, 0, false><<<dim3(HD / 128, 5, 1), 256>>>(
            x, Qwl, q, nullptr, NP1, HD, D_MODEL, D_MODEL, D_MODEL, HD, 0, 0, 0, 0, 1.f);
        mma_gemm<128, 128, 0, 0, false><<<dim3(HD / 128, 5, 1), 256>>>(
            x, Kwl, k, nullptr, NP1, HD, D_MODEL, D_MODEL, D_MODEL, HD, 0, 0, 0, 0, 1.f);
        mma_gemm<128, 128, 0, 0, false><<<dim3(HD / 128, 5, 1), 256>>>(
            x, Vwl, v, nullptr, NP1, HD, D_MODEL, D_MODEL, D_MODEL, HD, 0, 0, 0, 0, 1.f);

        // scores: per-head Q_h @ K_h^T * scale + bias -> attn [16,513,513]
        mma_gemm<128, 128, 2, 0, false><<<dim3(5, 5, N_HEAD), 256>>>(
            q, k, attn, bias, NP1, NP1, D_MODEL, HD, HD, NP1,
            D_MODEL, D_MODEL, (long)NP1 * NP1, (long)NCELL, scaling);

        softmax_kernel<<<N_HEAD * NP1, 256>>>();

        // O_h = attn_h @ V_h  (NN, K=513) -> o [513, 8192]
        mma_gemm<128, 128, 0, 1, false><<<dim3(4, 5, N_HEAD), 256>>>(
            attn, v, o, nullptr, NP1, D_MODEL, NP1, NP1, HD, HD,
            (long)NP1 * NP1, D_MODEL, D_MODEL, 0, 1.f);

        // z = o @ Wout^T : [513,8192] @ [512,8192]^T, split-K over 16 slices
        zero_float_kernel<<<(NP1 * D_MODEL + 255) / 256, 256>>>(z, NP1 * D_MODEL);
        mma_gemm<128, 128, 0, 0, true><<<dim3(4, 5, 16), 256>>>(
            o, Woutl, z, nullptr, NP1, D_MODEL, 512, HD, HD, D_MODEL,
            512, 512, 0, 0, 1.f);

        add_ln_kernel<<<NP1, 256>>>(x, z, ln1_s + l * D_MODEL, ln1_b + l * D_MODEL, x);

        // FF (64x64 tiles for more CTAs)
        mma_gemm<64, 64, 1, 0, false><<<dim3(8, 9, 1), 256>>>(
            x, F1l, h1, nullptr, NP1, D_MODEL, D_MODEL, D_MODEL, D_MODEL, D_MODEL,
            0, 0, 0, 0, 1.f);
        mma_gemm<64, 64, 0, 0, false><<<dim3(8, 9, 1), 256>>>(
            h1, F2l, z, nullptr, NP1, D_MODEL, D_MODEL, D_MODEL, D_MODEL, D_MODEL,
            0, 0, 0, 0, 1.f);

        float* lnout = (l == N_LAYER - 1) ? out : x;
        add_ln_kernel<<<NP1, 256>>>(x, z, ln2_s + l * D_MODEL, ln2_b + l * D_MODEL, lnout);
    }
}

// round 6
// speedup vs baseline: 2.2133x; 1.6590x over previous
#include <cuda_runtime.h>
#include <cuda_fp16.h>
#include <cuda_bf16.h>
#include <math.h>
#include <stdint.h>

// Problem constants
#define N_ATOM 512
#define D_MODEL 512
#define N_HEAD 16
#define K_GAUSS 128
#define M_EDGE 8
#define N_LAYER 4
#define NP1 513           // n + cls
#define HD (N_HEAD * D_MODEL)   // 8192
#define NCELL (N_ATOM * N_ATOM) // 262144

// ---------------- scratch (static device globals; no allocation) -------------
__device__ float g_psi[(size_t)NCELL * K_GAUSS];   // 134 MB
__device__ float g_T[(size_t)NCELL * K_GAUSS];     // 134 MB
__device__ float g_S[N_ATOM * K_GAUSS];
__device__ float g_bias[(size_t)N_HEAD * NCELL];   // 16.8 MB
__device__ int   g_et[NCELL];
__device__ int   g_deg[N_ATOM];
__device__ float g_x[NP1 * D_MODEL];
__device__ float g_q[(size_t)NP1 * HD];
__device__ float g_k[(size_t)NP1 * HD];
__device__ float g_v[(size_t)NP1 * HD];
__device__ float g_o[(size_t)NP1 * HD];
__device__ float g_attn[(size_t)N_HEAD * NP1 * NP1];
__device__ float g_z[NP1 * D_MODEL];
__device__ float g_h1[NP1 * D_MODEL];

// ---------------- small utility kernels --------------------------------------
__global__ void zero_int_kernel(int* p, int n) {
    int i = blockIdx.x * blockDim.x + threadIdx.x;
    if (i < n) p[i] = 0;
}
__global__ void zero_float_kernel(float* p, int n) {
    int i = blockIdx.x * blockDim.x + threadIdx.x;
    if (i < n) p[i] = 0.f;
}

// Ordered scatter, matching sequential last-write-wins semantics
__global__ void scatter_kernel(const int* __restrict__ edge_index,
                               const int* __restrict__ types, int E_) {
    if (blockIdx.x == 0 && threadIdx.x == 0) {
        for (int e = 0; e < E_; e++)
            g_et[edge_index[e] * N_ATOM + edge_index[E_ + e]] = types[e];
        for (int e = 0; e < E_; e++)
            g_et[edge_index[E_ + e] * N_ATOM + edge_index[e]] = types[e];
    }
}

__global__ void degree_kernel() {
    int i = blockIdx.x;
    int c = 0;
    for (int j = threadIdx.x; j < N_ATOM; j += 256)
        c += (g_et[i * N_ATOM + j] != 0);
    __shared__ int sh[256];
    sh[threadIdx.x] = c;
    __syncthreads();
    for (int s = 128; s > 0; s >>= 1) {
        if (threadIdx.x < s) sh[threadIdx.x] += sh[threadIdx.x + s];
        __syncthreads();
    }
    if (threadIdx.x == 0) g_deg[i] = sh[0];
}

__global__ void psi_kernel(const float* __restrict__ pos,
                           const float* __restrict__ gamma_tab,
                           const float* __restrict__ beta_tab,
                           const float* __restrict__ means,
                           const float* __restrict__ stds) {
    long cell = blockIdx.x;
    int k = threadIdx.x;
    int i = (int)(cell >> 9), j = (int)(cell & 511);
    float dx = pos[i * 3 + 0] - pos[j * 3 + 0];
    float dy = pos[i * 3 + 1] - pos[j * 3 + 1];
    float dz = pos[i * 3 + 2] - pos[j * 3 + 2];
    float dist = sqrtf(dx * dx + dy * dy + dz * dz + 1e-12f);
    int t = g_et[cell];
    float xg = gamma_tab[t] * dist + beta_tab[t];
    float sd = fabsf(stds[k]) + 0.01f;
    float u = (xg - means[k]) / sd;
    g_psi[cell * K_GAUSS + k] = (0.3989422804014327f / sd) * expf(-0.5f * u * u);
}

__global__ void psi_rowsum_kernel() {
    int i = blockIdx.x;
    int k = threadIdx.x; // 128
    float acc = 0.f;
    const float* base = g_psi + (size_t)i * N_ATOM * K_GAUSS + k;
    #pragma unroll 8
    for (int j = 0; j < N_ATOM; j++) acc += base[(size_t)j * K_GAUSS];
    g_S[i * K_GAUSS + k] = acc;
}

__global__ void bias_kernel(const int* __restrict__ spatial_pos,
                            const int* __restrict__ edge_input,
                            const float* __restrict__ spd_tab,
                            const float* __restrict__ edge_tab,
                            const float* __restrict__ edge_dis,
                            const float* __restrict__ pW2) {
    __shared__ float ew_s[M_EDGE * 256];
    __shared__ float etab_s[32 * 16];
    __shared__ float pW2_s[16 * 128];
    __shared__ float T_s[16][129];
    int tid = threadIdx.x; // 256
    for (int i = tid; i < M_EDGE * 256; i += 256) ew_s[i] = edge_dis[i];
    for (int i = tid; i < 32 * 16; i += 256) etab_s[i] = edge_tab[i];
    for (int i = tid; i < 16 * 128; i += 256) pW2_s[i] = pW2[i];
    long cell0 = (long)blockIdx.x * 16;
    for (int i = tid; i < 16 * 128; i += 256)
        T_s[i / 128][i % 128] = g_T[cell0 * K_GAUSS + i];
    __syncthreads();
    int cl = tid & 15, h = tid >> 4;
    long cell = cell0 + cl;
    float acc = 0.f;
    #pragma unroll 8
    for (int k = 0; k < 128; k++) acc += T_s[cl][k] * pW2_s[h * 128 + k];
    int sp = spatial_pos[cell];
    acc += spd_tab[sp * 16 + h];
    float esum = 0.f;
    for (int m = 0; m < M_EDGE; m++) {
        int ei = edge_input[cell * M_EDGE + m];
        const float* ewm = &ew_s[m * 256];
        #pragma unroll
        for (int hh = 0; hh < 16; hh++)
            esum += etab_s[ei * 16 + hh] * ewm[hh * 16 + h];
    }
    float spf = (sp == 0) ? 1.f : (float)sp;
    acc += esum / spf;
    g_bias[(size_t)h * NCELL + cell] = acc;
}

__global__ void xinit_kernel(const float* __restrict__ atoms_x,
                             const int* __restrict__ atoms,
                             const float* __restrict__ atom_tab,
                             const float* __restrict__ degree_tab,
                             const float* __restrict__ w3d,
                             const float* __restrict__ cls) {
    int i = blockIdx.x;
    __shared__ float Ssh[128];
    if (threadIdx.x < 128) Ssh[threadIdx.x] = g_S[i * K_GAUSS + threadIdx.x];
    __syncthreads();
    int a = atoms[i], dgi = g_deg[i];
    for (int d = threadIdx.x; d < D_MODEL; d += blockDim.x) {
        float acc = 0.f;
        const float* wrow = w3d + (size_t)d * K_GAUSS;
        #pragma unroll 8
        for (int k = 0; k < 128; k++) acc += Ssh[k] * wrow[k];
        g_x[(i + 1) * D_MODEL + d] = atoms_x[i * D_MODEL + d]
                                   + atom_tab[a * D_MODEL + d]
                                   + degree_tab[dgi * D_MODEL + d] + acc;
    }
    if (i == 0)
        for (int d = threadIdx.x; d < D_MODEL; d += blockDim.x)
            g_x[d] = cls[d];
}

// ---------------- tensor-core GEMM: fp16x3 (near-fp32 precision) ---------------
// C = alpha * A @ op(B) (+ epilogue). A and B each split into fp16 hi+lo
// (hi+lo is exact to ~2^-22). C ~= AhBh + AhBl + AlBh; dropped AlBl ~ 2^-22.
// EPI: 0 none, 1 gelu, 2 attn-bias add.
// BLOAD: 0 -> B is [N][ldb] (BT), 1 -> B is [K][ldb] (NN).
// ATOMIC: atomicAdd into C (split-K). VECA: float4 A loads (needs lda%4==0, K%16==0).
// Double-buffered smem, register-staged loads, one __syncthreads per chunk.

#define MMAF16(d, a, b) asm volatile( \
    "mma.sync.aligned.m16n8k16.row.col.f32.f16.f16.f32 " \
    "{%0,%1,%2,%3},{%4,%5,%6,%7},{%8,%9},{%0,%1,%2,%3};\n" \
    : "+f"(d[0]), "+f"(d[1]), "+f"(d[2]), "+f"(d[3]) \
    : "r"(a[0]), "r"(a[1]), "r"(a[2]), "r"(a[3]), "r"(b[0]), "r"(b[1]))

__device__ __forceinline__ void cvt_split2(__half* hi, __half* lo, float x0, float x1) {
    __half h0 = __float2half_rn(x0);
    __half h1 = __float2half_rn(x1);
    *(__half2*)hi = __halves2half2(h0, h1);
    *(__half2*)lo = __halves2half2(__float2half_rn(x0 - __half2float(h0)),
                                   __float2half_rn(x1 - __half2float(h1)));
}

template <int BM, int BN, int EPI, int BLOAD, bool ATOMIC, bool VECA>
__global__ __launch_bounds__(256) void mma_gemm(
    const float* __restrict__ Ag, const float* __restrict__ Bg,
    float* __restrict__ Cg, const float* __restrict__ biasg,
    int M, int N, int K, int lda, int ldb, int ldc,
    long strA, long strB, long strC, long strBias, float alpha) {

    constexpr int KC = 16;       // K per chunk
    constexpr int KS = 24;       // smem row stride (48B, conflict-free pattern)
    constexpr int WM = BM / 2;
    constexpr int WN = BN / 4;
    constexpr int MT = WM / 16;
    constexpr int NT = WN / 8;
    constexpr int A4 = (BM * KC) / (4 * 256);   // float4 loads per thread for A
    constexpr int B4 = (BN * KC) / (4 * 256);   // float4 loads per thread for B
    constexpr int NB4 = BN / 4;

    __shared__ __half smA_hi[2][BM][KS];
    __shared__ __half smA_lo[2][BM][KS];
    __shared__ __half smB_hi[2][BN][KS];
    __shared__ __half smB_lo[2][BN][KS];

    int bz = blockIdx.z;
    const float* A = Ag + (long)bz * strA;
    const float* B = Bg + (long)bz * strB;
    float* C = Cg + (long)bz * strC;
    const float* bias = (EPI == 2) ? (biasg + (long)bz * strBias) : nullptr;

    int bm = blockIdx.y * BM;
    int bn = blockIdx.x * BN;
    int tid = threadIdx.x;
    int wid = tid >> 5, lane = tid & 31;
    int wm = wid >> 2, wn = wid & 3;
    int g = lane >> 2, tg = lane & 3;

    float acc[MT][NT][4];
    #pragma unroll
    for (int i = 0; i < MT; i++)
        #pragma unroll
        for (int j = 0; j < NT; j++)
            #pragma unroll
            for (int t = 0; t < 4; t++) acc[i][j][t] = 0.f;

    float4 ra[A4], rb[B4];
    int nc = (K + KC - 1) / KC;

    // ---- load chunk c into registers
    auto loadA = [&](int c) {
        int k0 = c * KC;
        #pragma unroll
        for (int it = 0; it < A4; it++) {
            int idx = it * 256 + tid;
            int r = idx >> 2, c4 = idx & 3;
            int gm = bm + r;
            if (VECA) {
                if (gm < M)
                    ra[it] = *(const float4*)(A + (long)gm * lda + k0 + c4 * 4);
                else
                    ra[it] = make_float4(0.f, 0.f, 0.f, 0.f);
            } else {
                float e[4];
                #pragma unroll
                for (int q2 = 0; q2 < 4; q2++) {
                    int gk = k0 + c4 * 4 + q2;
                    e[q2] = (gm < M && gk < K) ? A[(long)gm * lda + gk] : 0.f;
                }
                ra[it] = make_float4(e[0], e[1], e[2], e[3]);
            }
        }
    };
    auto loadB = [&](int c) {
        int k0 = c * KC;
        if (BLOAD == 0) {
            #pragma unroll
            for (int it = 0; it < B4; it++) {
                int idx = it * 256 + tid;
                int r = idx >> 2, c4 = idx & 3;
                int gn = bn + r;
                if (gn < N)
                    rb[it] = *(const float4*)(B + (long)gn * ldb + k0 + c4 * 4);
                else
                    rb[it] = make_float4(0.f, 0.f, 0.f, 0.f);
            }
        } else {
            #pragma unroll
            for (int it = 0; it < B4; it++) {
                int idx = it * 256 + tid;
                int kk = idx / NB4, n4 = idx % NB4;
                int gk = k0 + kk;
                if (gk < K)
                    rb[it] = *(const float4*)(B + (long)gk * ldb + bn + n4 * 4);
                else
                    rb[it] = make_float4(0.f, 0.f, 0.f, 0.f);
            }
        }
    };
    auto storeAB = [&](int st) {
        #pragma unroll
        for (int it = 0; it < A4; it++) {
            int idx = it * 256 + tid;
            int r = idx >> 2, c4 = idx & 3;
            cvt_split2(&smA_hi[st][r][c4 * 4], &smA_lo[st][r][c4 * 4], ra[it].x, ra[it].y);
            cvt_split2(&smA_hi[st][r][c4 * 4 + 2], &smA_lo[st][r][c4 * 4 + 2], ra[it].z, ra[it].w);
        }
        if (BLOAD == 0) {
            #pragma unroll
            for (int it = 0; it < B4; it++) {
                int idx = it * 256 + tid;
                int r = idx >> 2, c4 = idx & 3;
                cvt_split2(&smB_hi[st][r][c4 * 4], &smB_lo[st][r][c4 * 4], rb[it].x, rb[it].y);
                cvt_split2(&smB_hi[st][r][c4 * 4 + 2], &smB_lo[st][r][c4 * 4 + 2], rb[it].z, rb[it].w);
            }
        } else {
            #pragma unroll
            for (int it = 0; it < B4; it++) {
                int idx = it * 256 + tid;
                int kk = idx / NB4, n4 = idx % NB4;
                float e[4] = {rb[it].x, rb[it].y, rb[it].z, rb[it].w};
                #pragma unroll
                for (int q2 = 0; q2 < 4; q2++) {
                    __half h = __float2half_rn(e[q2]);
                    smB_hi[st][n4 * 4 + q2][kk] = h;
                    smB_lo[st][n4 * 4 + q2][kk] = __float2half_rn(e[q2] - __half2float(h));
                }
            }
        }
    };

    // prologue
    loadA(0); loadB(0);
    storeAB(0);

    for (int c = 0; c < nc; c++) {
        __syncthreads();
        int st = c & 1;
        if (c + 1 < nc) { loadA(c + 1); loadB(c + 1); }

        uint32_t ah[MT][4], al[MT][4], bh[NT][2], bl[NT][2];
        int cc = tg * 2;
        #pragma unroll
        for (int mt = 0; mt < MT; mt++) {
            int row = wm * WM + mt * 16 + g;
            ah[mt][0] = *(const uint32_t*)&smA_hi[st][row][cc];
            ah[mt][1] = *(const uint32_t*)&smA_hi[st][row + 8][cc];
            ah[mt][2] = *(const uint32_t*)&smA_hi[st][row][cc + 8];
            ah[mt][3] = *(const uint32_t*)&smA_hi[st][row + 8][cc + 8];
            al[mt][0] = *(const uint32_t*)&smA_lo[st][row][cc];
            al[mt][1] = *(const uint32_t*)&smA_lo[st][row + 8][cc];
            al[mt][2] = *(const uint32_t*)&smA_lo[st][row][cc + 8];
            al[mt][3] = *(const uint32_t*)&smA_lo[st][row + 8][cc + 8];
        }
        #pragma unroll
        for (int nt = 0; nt < NT; nt++) {
            int col = wn * WN + nt * 8 + g;
            bh[nt][0] = *(const uint32_t*)&smB_hi[st][col][cc];
            bh[nt][1] = *(const uint32_t*)&smB_hi[st][col][cc + 8];
            bl[nt][0] = *(const uint32_t*)&smB_lo[st][col][cc];
            bl[nt][1] = *(const uint32_t*)&smB_lo[st][col][cc + 8];
        }
        #pragma unroll
        for (int mt = 0; mt < MT; mt++)
            #pragma unroll
            for (int nt = 0; nt < NT; nt++) {
                MMAF16(acc[mt][nt], ah[mt], bh[nt]);
                MMAF16(acc[mt][nt], ah[mt], bl[nt]);
                MMAF16(acc[mt][nt], al[mt], bh[nt]);
            }

        if (c + 1 < nc) storeAB((c + 1) & 1);
    }

    // ---- epilogue
    #pragma unroll
    for (int mt = 0; mt < MT; mt++) {
        #pragma unroll
        for (int nt = 0; nt < NT; nt++) {
            int r0 = bm + wm * WM + mt * 16 + g;
            int c0 = bn + wn * WN + nt * 8 + tg * 2;
            #pragma unroll
            for (int t = 0; t < 4; t++) {
                int gm = r0 + (t >= 2 ? 8 : 0);
                int gn = c0 + (t & 1);
                if (gm >= M || gn >= N) continue;
                float vv = acc[mt][nt][t] * alpha;
                if (EPI == 1) {
                    vv = 0.5f * vv * (1.f + erff(vv * 0.7071067811865476f));
                } else if (EPI == 2) {
                    if (gm >= 1 && gn >= 1)
                        vv += bias[(long)(gm - 1) * N_ATOM + (gn - 1)];
                }
                if (ATOMIC) atomicAdd(&C[(long)gm * ldc + gn], vv);
                else C[(long)gm * ldc + gn] = vv;
            }
        }
    }
}

// ---------------- softmax over rows of length 513 ------------------------------
__global__ void softmax_kernel() {
    long row = blockIdx.x;
    float* p = g_attn + row * NP1;
    int tid = threadIdx.x; // 256
    __shared__ float sh[256];
    float mx = -1e30f;
    for (int m = tid; m < NP1; m += 256) mx = fmaxf(mx, p[m]);
    sh[tid] = mx; __syncthreads();
    for (int s = 128; s > 0; s >>= 1) {
        if (tid < s) sh[tid] = fmaxf(sh[tid], sh[tid + s]);
        __syncthreads();
    }
    mx = sh[0]; __syncthreads();
    float sum = 0.f;
    for (int m = tid; m < NP1; m += 256) {
        float e = expf(p[m] - mx);
        p[m] = e;
        sum += e;
    }
    sh[tid] = sum; __syncthreads();
    for (int s = 128; s > 0; s >>= 1) {
        if (tid < s) sh[tid] += sh[tid + s];
        __syncthreads();
    }
    float inv = 1.f / sh[0];
    __syncthreads();
    for (int m = tid; m < NP1; m += 256) p[m] *= inv;
}

// ---------------- residual add + layernorm ------------------------------------
__global__ void add_ln_kernel(const float* __restrict__ xin, const float* __restrict__ z,
                              const float* __restrict__ s, const float* __restrict__ b,
                              float* __restrict__ xout) {
    int row = blockIdx.x, tid = threadIdx.x; // 256 threads, 512 cols
    float v0 = xin[row * D_MODEL + tid] + z[row * D_MODEL + tid];
    float v1 = xin[row * D_MODEL + tid + 256] + z[row * D_MODEL + tid + 256];
    __shared__ float sh[256];
    sh[tid] = v0 + v1; __syncthreads();
    for (int st = 128; st > 0; st >>= 1) {
        if (tid < st) sh[tid] += sh[tid + st];
        __syncthreads();
    }
    float mu = sh[0] * (1.f / D_MODEL);
    __syncthreads();
    float d0 = v0 - mu, d1 = v1 - mu;
    sh[tid] = d0 * d0 + d1 * d1; __syncthreads();
    for (int st = 128; st > 0; st >>= 1) {
        if (tid < st) sh[tid] += sh[tid + st];
        __syncthreads();
    }
    float rstd = rsqrtf(sh[0] * (1.f / D_MODEL) + 1e-5f);
    xout[row * D_MODEL + tid]       = d0 * rstd * s[tid]       + b[tid];
    xout[row * D_MODEL + tid + 256] = d1 * rstd * s[tid + 256] + b[tid + 256];
}

// ---------------- host launch ---------------------------------------------------
extern "C" void kernel_launch(void* const* d_in, const int* in_sizes, int n_in,
                              void* d_out, int out_size) {
    const float* atoms_x  = (const float*)d_in[0];
    const float* pos      = (const float*)d_in[1];
    const int*   atoms    = (const int*)d_in[2];
    const int*   edge_index = (const int*)d_in[3];
    const int*   edge_attr_types = (const int*)d_in[4];
    const int*   spatial_pos = (const int*)d_in[5];
    const int*   edge_input  = (const int*)d_in[6];
    const float* atom_tab   = (const float*)d_in[7];
    const float* degree_tab = (const float*)d_in[8];
    const float* w3d        = (const float*)d_in[9];
    const float* spd_tab    = (const float*)d_in[10];
    const float* edge_tab   = (const float*)d_in[11];
    const float* edge_dis   = (const float*)d_in[12];
    const float* means      = (const float*)d_in[13];
    const float* stds       = (const float*)d_in[14];
    const float* gamma_tab  = (const float*)d_in[15];
    const float* beta_tab   = (const float*)d_in[16];
    const float* pW1        = (const float*)d_in[17];
    const float* pW2        = (const float*)d_in[18];
    const float* cls        = (const float*)d_in[19];
    const float* Qw         = (const float*)d_in[20];
    const float* Kw         = (const float*)d_in[21];
    const float* Vw         = (const float*)d_in[22];
    const float* Wout       = (const float*)d_in[23];
    const float* F1         = (const float*)d_in[24];
    const float* F2         = (const float*)d_in[25];
    const float* ln1_s      = (const float*)d_in[26];
    const float* ln1_b      = (const float*)d_in[27];
    const float* ln2_s      = (const float*)d_in[28];
    const float* ln2_b      = (const float*)d_in[29];
    float* out = (float*)d_out;

    float *psi, *T, *bias, *x, *q, *k, *v, *o, *attn, *z, *h1;
    int *et;
    cudaGetSymbolAddress((void**)&psi,  g_psi);
    cudaGetSymbolAddress((void**)&T,    g_T);
    cudaGetSymbolAddress((void**)&bias, g_bias);
    cudaGetSymbolAddress((void**)&x,    g_x);
    cudaGetSymbolAddress((void**)&q,    g_q);
    cudaGetSymbolAddress((void**)&k,    g_k);
    cudaGetSymbolAddress((void**)&v,    g_v);
    cudaGetSymbolAddress((void**)&o,    g_o);
    cudaGetSymbolAddress((void**)&attn, g_attn);
    cudaGetSymbolAddress((void**)&z,    g_z);
    cudaGetSymbolAddress((void**)&h1,   g_h1);
    cudaGetSymbolAddress((void**)&et,   g_et);

    const float scaling = 0.17677669529663687f; // (512/16)^-0.5

    // ---- graph preprocessing ----
    zero_int_kernel<<<(NCELL + 255) / 256, 256>>>(et, NCELL);
    scatter_kernel<<<1, 1>>>(edge_index, edge_attr_types, 2048);
    degree_kernel<<<N_ATOM, 256>>>();
    psi_kernel<<<NCELL, K_GAUSS>>>(pos, gamma_tab, beta_tab, means, stds);
    psi_rowsum_kernel<<<N_ATOM, K_GAUSS>>>();
    // T = gelu(psi @ pW1^T)   [262144,128] x [128,128]^T
    mma_gemm<128, 128, 1, 0, false, true><<<dim3(1, NCELL / 128, 1), 256>>>(
        psi, pW1, T, nullptr, NCELL, K_GAUSS, K_GAUSS, K_GAUSS, K_GAUSS, K_GAUSS,
        0, 0, 0, 0, 1.f);
    bias_kernel<<<NCELL / 16, 256>>>(spatial_pos, edge_input, spd_tab, edge_tab,
                                     edge_dis, pW2);
    xinit_kernel<<<N_ATOM, 256>>>(atoms_x, atoms, atom_tab, degree_tab, w3d, cls);

    // ---- transformer layers ----
    for (int l = 0; l < N_LAYER; l++) {
        const float* Qwl = Qw + (size_t)l * HD * D_MODEL;
        const float* Kwl = Kw + (size_t)l * HD * D_MODEL;
        const float* Vwl = Vw + (size_t)l * HD * D_MODEL;
        const float* Woutl = Wout + (size_t)l * D_MODEL * HD;
        const float* F1l = F1 + (size_t)l * D_MODEL * D_MODEL;
        const float* F2l = F2 + (size_t)l * D_MODEL * D_MODEL;

        // Q/K/V: [513,512] @ [8192,512]^T -> [513,8192]
        mma_gemm<128, 128, 0, 0, false, true><<<dim3(HD / 128, 5, 1), 256>>>(
            x, Qwl, q, nullptr, NP1, HD, D_MODEL, D_MODEL, D_MODEL, HD, 0, 0, 0, 0, 1.f);
        mma_gemm<128, 128, 0, 0, false, true><<<dim3(HD / 128, 5, 1), 256>>>(
            x, Kwl, k, nullptr, NP1, HD, D_MODEL, D_MODEL, D_MODEL, HD, 0, 0, 0, 0, 1.f);
        mma_gemm<128, 128, 0, 0, false, true><<<dim3(HD / 128, 5, 1), 256>>>(
            x, Vwl, v, nullptr, NP1, HD, D_MODEL, D_MODEL, D_MODEL, HD, 0, 0, 0, 0, 1.f);

        // scores: per-head Q_h @ K_h^T * scale + bias -> attn [16,513,513]
        mma_gemm<128, 128, 2, 0, false, true><<<dim3(5, 5, N_HEAD), 256>>>(
            q, k, attn, bias, NP1, NP1, D_MODEL, HD, HD, NP1,
            D_MODEL, D_MODEL, (long)NP1 * NP1, (long)NCELL, scaling);

        softmax_kernel<<<N_HEAD * NP1, 256>>>();

        // O_h = attn_h @ V_h  (NN, K=513, lda=513 -> scalar A loads) -> o [513, 8192]
        mma_gemm<128, 128, 0, 1, false, false><<<dim3(4, 5, N_HEAD), 256>>>(
            attn, v, o, nullptr, NP1, D_MODEL, NP1, NP1, HD, HD,
            (long)NP1 * NP1, D_MODEL, D_MODEL, 0, 1.f);

        // z = o @ Wout^T : [513,8192] @ [512,8192]^T, split-K over 16 slices
        zero_float_kernel<<<(NP1 * D_MODEL + 255) / 256, 256>>>(z, NP1 * D_MODEL);
        mma_gemm<128, 128, 0, 0, true, true><<<dim3(4, 5, 16), 256>>>(
            o, Woutl, z, nullptr, NP1, D_MODEL, 512, HD, HD, D_MODEL,
            512, 512, 0, 0, 1.f);

        add_ln_kernel<<<NP1, 256>>>(x, z, ln1_s + l * D_MODEL, ln1_b + l * D_MODEL, x);

        // FF (64x64 tiles for more CTAs)
        mma_gemm<64, 64, 1, 0, false, true><<<dim3(8, 9, 1), 256>>>(
            x, F1l, h1, nullptr, NP1, D_MODEL, D_MODEL, D_MODEL, D_MODEL, D_MODEL,
            0, 0, 0, 0, 1.f);
        mma_gemm<64, 64, 0, 0, false, true><<<dim3(8, 9, 1), 256>>>(
            h1, F2l, z, nullptr, NP1, D_MODEL, D_MODEL, D_MODEL, D_MODEL, D_MODEL,
            0, 0, 0, 0, 1.f);

        float* lnout = (l == N_LAYER - 1) ? out : x;
        add_ln_kernel<<<NP1, 256>>>(x, z, ln2_s + l * D_MODEL, ln2_b + l * D_MODEL, lnout);
    }
}